// round 9
// baseline (speedup 1.0000x reference)
#include <cuda_runtime.h>
#include <cfloat>

// 101-layer chain h <- relu(w*h + b), w > 0, collapses exactly to a single
// clamped affine. OUTPUT-SPACE form (division-free composition):
//   f(x) = max(S*x + O, F)
//   layer i: (S,O,F) = (w_i, b_i, 0)
//   g o f :  S' = Sg*Sf,  O' = Sg*Of + Og,  F' = max(Sg*Ff + Og, Fg)
// Composition is 2 FMA + 1 FMAX — no MUFU divides anywhere.
//
// R9 = R7 structure (flat, 4 float4/thread, per-warp redundant shuffle scan,
// no barrier) with the division-free scan.

__global__ __launch_bounds__(256)
void fused_flat4_of_kernel(const float4* __restrict__ x4,
                           float4* __restrict__ o4,
                           const float* __restrict__ w,
                           const float* __restrict__ b,
                           int n_layers, int n4, int n,
                           const float* __restrict__ x,
                           float* __restrict__ out) {
    const int tid  = threadIdx.x;
    const int lane = tid & 31;
    const int base = blockIdx.x * 1024 + tid;

    // Prefetch all four elements FIRST: DRAM latency overlaps the scan.
    float4 v0, v1, v2, v3;
    const bool ok0 = (base       < n4);
    const bool ok1 = (base + 256 < n4);
    const bool ok2 = (base + 512 < n4);
    const bool ok3 = (base + 768 < n4);
    if (ok0) v0 = x4[base];
    if (ok1) v1 = x4[base + 256];
    if (ok2) v2 = x4[base + 512];
    if (ok3) v3 = x4[base + 768];

    // ---- per-warp division-free shuffle scan (up to 128 layers) ----
    // Identity: S=1, O=0, F=-inf
    float S = 1.0f, O = 0.0f, F = -FLT_MAX;
    #pragma unroll
    for (int k = 0; k < 4; ++k) {
        const int idx = 4 * lane + k;             // independent loads
        if (idx < n_layers) {
            const float wi = w[idx];              // layer: (wi, bi, 0)
            const float bi = b[idx];
            // compose layer AFTER current accumulator: new = layer o acc
            F = fmaxf(fmaf(wi, F, bi), 0.0f);
            O = fmaf(wi, O, bi);
            S = wi * S;
        }
    }
    #pragma unroll
    for (int d = 1; d < 32; d <<= 1) {
        const float Sp = __shfl_up_sync(0xffffffffu, S, d);
        const float Op = __shfl_up_sync(0xffffffffu, O, d);
        const float Fp = __shfl_up_sync(0xffffffffu, F, d);
        if (lane >= d) {
            // self (later layers) o predecessor (earlier layers)
            F = fmaxf(fmaf(S, Fp, O), F);
            O = fmaf(S, Op, O);
            S = S * Sp;
        }
    }
    // broadcast lane 31's inclusive result to the whole warp
    S = __shfl_sync(0xffffffffu, S, 31);
    O = __shfl_sync(0xffffffffu, O, 31);
    F = __shfl_sync(0xffffffffu, F, 31);

    float4 r;
    if (ok0) {
        r.x = fmaxf(fmaf(S, v0.x, O), F); r.y = fmaxf(fmaf(S, v0.y, O), F);
        r.z = fmaxf(fmaf(S, v0.z, O), F); r.w = fmaxf(fmaf(S, v0.w, O), F);
        o4[base] = r;
    }
    if (ok1) {
        r.x = fmaxf(fmaf(S, v1.x, O), F); r.y = fmaxf(fmaf(S, v1.y, O), F);
        r.z = fmaxf(fmaf(S, v1.z, O), F); r.w = fmaxf(fmaf(S, v1.w, O), F);
        o4[base + 256] = r;
    }
    if (ok2) {
        r.x = fmaxf(fmaf(S, v2.x, O), F); r.y = fmaxf(fmaf(S, v2.y, O), F);
        r.z = fmaxf(fmaf(S, v2.z, O), F); r.w = fmaxf(fmaf(S, v2.w, O), F);
        o4[base + 512] = r;
    }
    if (ok3) {
        r.x = fmaxf(fmaf(S, v3.x, O), F); r.y = fmaxf(fmaf(S, v3.y, O), F);
        r.z = fmaxf(fmaf(S, v3.z, O), F); r.w = fmaxf(fmaf(S, v3.w, O), F);
        o4[base + 768] = r;
    }

    // scalar tail (n % 4 != 0) — negligible
    if (blockIdx.x == 0 && tid == 0) {
        for (int j = n4 * 4; j < n; ++j) {
            out[j] = fmaxf(fmaf(S, x[j], O), F);
        }
    }
}

extern "C" void kernel_launch(void* const* d_in, const int* in_sizes, int n_in,
                              void* d_out, int out_size) {
    const float* x = (const float*)d_in[0];
    const float* w = (const float*)d_in[1];
    const float* b = (const float*)d_in[2];
    float* out = (float*)d_out;

    const int n        = in_sizes[0];
    const int n_layers = in_sizes[1];
    const int n4       = n / 4;

    const int threads = 256;
    const int blocks  = (n4 + 1023) / 1024;   // 4 float4 per thread

    fused_flat4_of_kernel<<<blocks, threads>>>(
        (const float4*)x, (float4*)out, w, b, n_layers, n4, n, x, out);
}